// round 16
// baseline (speedup 1.0000x reference)
#include <cuda_runtime.h>
#include <cuda_fp16.h>
#include <cstdint>

#define NN   50000
#define EE   600000
#define FEAT 11
#define DD   128
#define BBATCH 500
#define MAXA 100
#define NLAYERS 5
#define DENSE (BBATCH*MAXA*DD)   /* 6,400,000 */
#define MASKN (BBATCH*MAXA)      /* 50,000 */

#define SCAN_BS   1024
#define SCAN_NB   ((NN + SCAN_BS - 1) / SCAN_BS)   /* 49 */
#define SCAN_FLAG (1 << 30)

#define TILE_M    128
#define GEMM_NB   ((NN + TILE_M - 1) / TILE_M)     /* 391 */
#define NNP       (GEMM_NB * TILE_M)               /* 50048, padded */

// merged-kernel block ranges
#define PWB  ((NLAYERS*DD*DD + 255)/256)           /* 320  prepw blocks  */
#define HB   ((EE + 255)/256)                      /* 2344 hist blocks   */
#define CSRB ((EE + 255)/256)                      /* 2344 csr blocks    */
#define EXPB ((NN + 31)/32)                        /* 1563 expand blocks (4 nodes/warp) */

// -------- scratch (static device globals; zero-initialized, no runtime alloc) --------
// INVARIANT across graph replays: g_deg == 0, g_counts == 0, g_bsum == 0 at entry.
__device__ __half g_y[NN*DD];                  // y = dinv * x, fp16 (12.8 MB)
__device__ __half g_apk[NNP*DD];               // aggregated A, fp16 (pad rows stay 0)
__device__ __half g_wpk[NLAYERS*DD*DD];        // Wt [l][n][k] fp16, fragment-paired word order
__device__ float g_dinv[NN];
__device__ int   g_deg[NN];
__device__ int   g_rowstart[NN+1];
__device__ int   g_cursor[NN];
__device__ int   g_csr_src[EE];
__device__ int   g_counts[BBATCH];
__device__ int   g_ptr[BBATCH];
__device__ int   g_bsum[SCAN_NB];

// ---------------- prep: W transpose + degree/count histogram (merged) ----------------
__global__ void k_prep_hist(const float* __restrict__ Ws,
                            const int* __restrict__ col, const int* __restrict__ batch)
{
    if (blockIdx.x < PWB) {
        int idx = blockIdx.x * 256 + threadIdx.x;
        if (idx >= NLAYERS*DD*DD) return;
        int l = idx >> 14;
        int r = idx & 16383;
        int n = r >> 7;
        int k = r & 127;
        float v = Ws[l*DD*DD + k*DD + n];
        int w = k >> 1;
        int p = ((w >> 3) << 2) | (w & 3);
        int c = (w >> 2) & 1;
        int dst = (l*DD + n) * DD + p*4 + c*2 + (k & 1);
        g_wpk[dst] = __float2half_rn(v);
        return;
    }
    int i = (blockIdx.x - PWB) * 256 + threadIdx.x;
    if (i < EE) atomicAdd(&g_deg[col[i]], 1);
    if (i < NN) atomicAdd(&g_counts[batch[i]], 1);
}

// -------- fused scan: local scan + flagged publish + predecessor poll + apply --------
__global__ __launch_bounds__(SCAN_BS)
void k_scan()
{
    __shared__ int warp_sums[32];
    __shared__ int s_boff;
    int tid  = threadIdx.x;
    int lane = tid & 31;
    int wid  = tid >> 5;
    int i    = blockIdx.x * SCAN_BS + tid;

    int v0 = (i < NN) ? g_deg[i] : 0;
    if (i < NN) {
        g_dinv[i] = rsqrtf((float)v0 + 2.0f);
        g_deg[i]  = 0;                       // restore invariant
    }
    int v  = v0;
    #pragma unroll
    for (int off = 1; off < 32; off <<= 1) {
        int t = __shfl_up_sync(0xffffffffu, v, off);
        if (lane >= off) v += t;
    }
    if (lane == 31) warp_sums[wid] = v;
    __syncthreads();
    if (wid == 0) {
        int s = warp_sums[lane];
        #pragma unroll
        for (int off = 1; off < 32; off <<= 1) {
            int t = __shfl_up_sync(0xffffffffu, s, off);
            if (lane >= off) s += t;
        }
        warp_sums[lane] = s;
    }
    __syncthreads();
    int incl = v + (wid ? warp_sums[wid-1] : 0);

    if (tid == 0) {
        int total = warp_sums[31];
        atomicExch(&g_bsum[blockIdx.x], total | SCAN_FLAG);
    }

    if (wid == 1) {
        int sum = 0;
        for (int p = lane; p < blockIdx.x; p += 32) {
            int bv;
            do { bv = atomicAdd(&g_bsum[p], 0); } while (!(bv & SCAN_FLAG));
            sum += bv & ~SCAN_FLAG;
        }
        #pragma unroll
        for (int off = 16; off > 0; off >>= 1)
            sum += __shfl_down_sync(0xffffffffu, sum, off);
        if (lane == 0) s_boff = sum;
    }
    __syncthreads();
    int boff = s_boff;

    if (i < NN) {
        g_rowstart[i+1] = incl + boff;
        g_cursor[i]     = incl - v0 + boff;
    }

    if (blockIdx.x == 0) {
        if (tid == 0) g_rowstart[0] = 0;
        int c = (tid < BBATCH) ? g_counts[tid] : 0;
        int vv = c;
        #pragma unroll
        for (int off = 1; off < 32; off <<= 1) {
            int t = __shfl_up_sync(0xffffffffu, vv, off);
            if (lane >= off) vv += t;
        }
        __syncthreads();
        if (lane == 31) warp_sums[wid] = vv;
        __syncthreads();
        if (wid == 0) {
            int s = warp_sums[lane];
            #pragma unroll
            for (int off = 1; off < 32; off <<= 1) {
                int t = __shfl_up_sync(0xffffffffu, s, off);
                if (lane >= off) s += t;
            }
            warp_sums[lane] = s;
        }
        __syncthreads();
        int incl2 = vv + (wid ? warp_sums[wid-1] : 0);
        if (tid < BBATCH) {
            g_ptr[tid]    = incl2 - c;
            g_counts[tid] = 0;
        }
    }
}

// ---- merged: csr build + mask write + log-expansion (4 nodes/warp) ----
__global__ __launch_bounds__(256)
void k_csr_expand(const int* __restrict__ conn, const int* __restrict__ batch,
                  float* __restrict__ out, int out_size,
                  const float* __restrict__ atoms,
                  const float* __restrict__ Wexp,
                  const float* __restrict__ bexp)
{
    __shared__ float sW[FEAT*DD];
    __shared__ float sb[DD];

    if (blockIdx.x < CSRB) {
        int e = blockIdx.x * 256 + threadIdx.x;
        if (blockIdx.x == 0 && threadIdx.x < SCAN_NB)
            g_bsum[threadIdx.x] = 0;
        if (e < NN && out_size >= DENSE + MASKN) {
            int b = batch[e];
            out[DENSE + b*MAXA + (e - g_ptr[b])] = 1.0f;
        }
        if (e >= EE) return;
        int r = conn[e];
        int c = conn[EE + e];
        int slot = atomicAdd(&g_cursor[c], 1);
        g_csr_src[slot] = r;
        return;
    }

    int tid = threadIdx.x;
    for (int i = tid; i < FEAT*DD; i += 256) sW[i] = Wexp[i];
    if (tid < DD) sb[tid] = bexp[tid];
    __syncthreads();

    int nb   = blockIdx.x - CSRB;
    int wid  = tid >> 5;
    int lane = tid & 31;
    int d0   = lane * 4;

    #pragma unroll
    for (int it = 0; it < 4; it++) {
        int n = nb * 32 + wid * 4 + it;
        if (n >= NN) break;

        float la = 0.f;
        if (lane < FEAT) la = logf(atoms[n*FEAT + lane] + 1.0f);

        float acc[4];
        #pragma unroll
        for (int q = 0; q < 4; q++) acc[q] = sb[d0 + q];
        #pragma unroll
        for (int f = 0; f < FEAT; f++) {
            float lf = __shfl_sync(0xffffffffu, la, f);
            #pragma unroll
            for (int q = 0; q < 4; q++)
                acc[q] = fmaf(lf, sW[f*DD + d0 + q], acc[q]);
        }
        float di = g_dinv[n];
        __half2 h0 = __floats2half2_rn(acc[0]*di, acc[1]*di);
        __half2 h1 = __floats2half2_rn(acc[2]*di, acc[3]*di);
        uint2 p;
        p.x = *reinterpret_cast<uint32_t*>(&h0);
        p.y = *reinterpret_cast<uint32_t*>(&h1);
        reinterpret_cast<uint2*>(g_y)[n*32 + lane] = p;
    }
}

// ------- aggregation: agg[w] = dinv[w]*(sum_src y[src] + 2*y[w]) -------
// Indices loaded once per 32-chunk (coalesced, lane-distributed) and broadcast via
// shuffle — zero per-edge index LDGs. Gathers 8-deep; edge pairs pre-summed in
// fp16 (same pairing as before -> bit-identical numerics).
__global__ void k_agg(const __half* __restrict__ y)
{
    int w = (blockIdx.x * blockDim.x + threadIdx.x) >> 5;
    if (w >= NN) return;
    int lane = threadIdx.x & 31;
    const uint2* yr = reinterpret_cast<const uint2*>(y);

    uint2 sv = yr[w*32 + lane];
    float2 s0 = __half22float2(*reinterpret_cast<__half2*>(&sv.x));
    float2 s1 = __half22float2(*reinterpret_cast<__half2*>(&sv.y));
    float4 acc = make_float4(2.f*s0.x, 2.f*s0.y, 2.f*s1.x, 2.f*s1.y);

    int s = g_rowstart[w];
    int e = g_rowstart[w+1];

    for (int base = s; base < e; base += 32) {
        int rem = e - base;
        int cnt = rem < 32 ? rem : 32;
        int myidx = 0;
        if (base + lane < e) myidx = g_csr_src[base + lane];

        int q = 0;
        for (; q + 8 <= cnt; q += 8) {
            int id[8];
            #pragma unroll
            for (int t = 0; t < 8; t++) id[t] = __shfl_sync(0xffffffffu, myidx, q + t);
            uint2 u[8];
            #pragma unroll
            for (int t = 0; t < 8; t++) u[t] = yr[id[t]*32 + lane];
            #pragma unroll
            for (int t = 0; t < 4; t++) {
                __half2 px = __hadd2(*reinterpret_cast<__half2*>(&u[2*t].x),
                                     *reinterpret_cast<__half2*>(&u[2*t+1].x));
                __half2 py = __hadd2(*reinterpret_cast<__half2*>(&u[2*t].y),
                                     *reinterpret_cast<__half2*>(&u[2*t+1].y));
                float2 fx = __half22float2(px);
                float2 fy = __half22float2(py);
                acc.x += fx.x; acc.y += fx.y; acc.z += fy.x; acc.w += fy.y;
            }
        }
        for (; q + 2 <= cnt; q += 2) {
            int i0 = __shfl_sync(0xffffffffu, myidx, q);
            int i1 = __shfl_sync(0xffffffffu, myidx, q + 1);
            uint2 u0 = yr[i0*32 + lane];
            uint2 u1 = yr[i1*32 + lane];
            __half2 px = __hadd2(*reinterpret_cast<__half2*>(&u0.x),
                                 *reinterpret_cast<__half2*>(&u1.x));
            __half2 py = __hadd2(*reinterpret_cast<__half2*>(&u0.y),
                                 *reinterpret_cast<__half2*>(&u1.y));
            float2 fx = __half22float2(px);
            float2 fy = __half22float2(py);
            acc.x += fx.x; acc.y += fx.y; acc.z += fy.x; acc.w += fy.y;
        }
        if (q < cnt) {
            int i0 = __shfl_sync(0xffffffffu, myidx, q);
            uint2 u = yr[i0*32 + lane];
            float2 a = __half22float2(*reinterpret_cast<__half2*>(&u.x));
            float2 b = __half22float2(*reinterpret_cast<__half2*>(&u.y));
            acc.x += a.x; acc.y += a.y; acc.z += b.x; acc.w += b.y;
        }
    }

    float di = g_dinv[w];
    __half2 h0 = __floats2half2_rn(acc.x*di, acc.y*di);
    __half2 h1 = __floats2half2_rn(acc.z*di, acc.w*di);
    uint2 p;
    p.x = *reinterpret_cast<uint32_t*>(&h0);
    p.y = *reinterpret_cast<uint32_t*>(&h1);
    reinterpret_cast<uint2*>(g_apk)[w*32 + lane] = p;
}

// ---------------- fp16 mma.sync GEMM (single term): relu(A W^T + b) ----------------
__device__ __forceinline__ void mma_f16(float* d, const uint32_t* a, const uint32_t* b)
{
    asm volatile(
        "mma.sync.aligned.m16n8k16.row.col.f32.f16.f16.f32 "
        "{%0,%1,%2,%3}, {%4,%5,%6,%7}, {%8,%9}, {%0,%1,%2,%3};"
        : "+f"(d[0]), "+f"(d[1]), "+f"(d[2]), "+f"(d[3])
        : "r"(a[0]), "r"(a[1]), "r"(a[2]), "r"(a[3]), "r"(b[0]), "r"(b[1]));
}

// non-LAST: writes y = dinv*relu(..) as fp16. LAST: scatters fp32 into dense out.
template<bool LAST>
__global__ __launch_bounds__(256)
void k_gemm_mma(const __half* __restrict__ apk,
                const __half* __restrict__ wpk,
                const float* __restrict__ bias,
                __half* __restrict__ yout,
                float* __restrict__ dout,
                const int* __restrict__ batch)
{
    int tid    = threadIdx.x;
    int lane   = tid & 31;
    int wid    = tid >> 5;
    int warp_m = wid & 3;
    int warp_n = wid >> 2;
    int g      = lane >> 2;
    int tq     = lane & 3;

    int rowBase = blockIdx.x * TILE_M + warp_m * 32;
    int colBase = warp_n * 64;

    const uint32_t* AP = reinterpret_cast<const uint32_t*>(apk);
    const uint2*    BP = reinterpret_cast<const uint2*>(wpk);

    const uint32_t* a0 = AP + (rowBase + g     ) * 64;
    const uint32_t* a1 = AP + (rowBase + g +  8) * 64;
    const uint32_t* a2 = AP + (rowBase + g + 16) * 64;
    const uint32_t* a3 = AP + (rowBase + g + 24) * 64;
    const uint2*    bp = BP + (colBase + g) * 32;

    float d[2][8][4];
    #pragma unroll
    for (int mt = 0; mt < 2; mt++)
        #pragma unroll
        for (int nt = 0; nt < 8; nt++)
            #pragma unroll
            for (int q = 0; q < 4; q++) d[mt][nt][q] = 0.0f;

    #pragma unroll 4
    for (int ks = 0; ks < 8; ks++) {
        int o0 = ks*8 + tq;
        int o1 = o0 + 4;

        uint32_t aF[2][4];
        aF[0][0] = a0[o0]; aF[0][1] = a1[o0]; aF[0][2] = a0[o1]; aF[0][3] = a1[o1];
        aF[1][0] = a2[o0]; aF[1][1] = a3[o0]; aF[1][2] = a2[o1]; aF[1][3] = a3[o1];

        uint32_t bF[8][2];
        #pragma unroll
        for (int nt = 0; nt < 8; nt++) {
            uint2 wv = bp[nt*256 + ks*4 + tq];
            bF[nt][0] = wv.x; bF[nt][1] = wv.y;
        }
        #pragma unroll
        for (int mt = 0; mt < 2; mt++)
            #pragma unroll
            for (int nt = 0; nt < 8; nt++)
                mma_f16(d[mt][nt], aF[mt], bF[nt]);
    }

    #pragma unroll
    for (int mt = 0; mt < 2; mt++) {
        int m0 = rowBase + mt*16 + g;
        int m1 = m0 + 8;
        if (LAST) {
            int or0 = 0, or1 = 0;
            if (m0 < NN) { int b = batch[m0]; or0 = b*MAXA + (m0 - g_ptr[b]); }
            if (m1 < NN) { int b = batch[m1]; or1 = b*MAXA + (m1 - g_ptr[b]); }
            #pragma unroll
            for (int nt = 0; nt < 8; nt++) {
                int cn = colBase + nt*8 + tq*2;
                float2 bv = *reinterpret_cast<const float2*>(bias + cn);
                if (m0 < NN) {
                    float2 o;
                    o.x = fmaxf(d[mt][nt][0] + bv.x, 0.f);
                    o.y = fmaxf(d[mt][nt][1] + bv.y, 0.f);
                    *reinterpret_cast<float2*>(dout + or0*DD + cn) = o;
                }
                if (m1 < NN) {
                    float2 o;
                    o.x = fmaxf(d[mt][nt][2] + bv.x, 0.f);
                    o.y = fmaxf(d[mt][nt][3] + bv.y, 0.f);
                    *reinterpret_cast<float2*>(dout + or1*DD + cn) = o;
                }
            }
        } else {
            float di0 = (m0 < NN) ? g_dinv[m0] : 0.f;
            float di1 = (m1 < NN) ? g_dinv[m1] : 0.f;
            #pragma unroll
            for (int nt = 0; nt < 8; nt++) {
                int cn = colBase + nt*8 + tq*2;
                float2 bv = *reinterpret_cast<const float2*>(bias + cn);
                if (m0 < NN) {
                    float ox = fmaxf(d[mt][nt][0] + bv.x, 0.f) * di0;
                    float oy = fmaxf(d[mt][nt][1] + bv.y, 0.f) * di0;
                    *reinterpret_cast<__half2*>(yout + m0*DD + cn) = __floats2half2_rn(ox, oy);
                }
                if (m1 < NN) {
                    float ox = fmaxf(d[mt][nt][2] + bv.x, 0.f) * di1;
                    float oy = fmaxf(d[mt][nt][3] + bv.y, 0.f) * di1;
                    *reinterpret_cast<__half2*>(yout + m1*DD + cn) = __floats2half2_rn(ox, oy);
                }
            }
        }
    }
}

// ---------------- tail zero (only for any region beyond dense+mask) ----------------
__global__ void k_zero_tail(float* __restrict__ out, int start, int n)
{
    int i = blockIdx.x * blockDim.x + threadIdx.x;
    if (i < n) out[start + i] = 0.0f;
}

// ---------------- launch ----------------
extern "C" void kernel_launch(void* const* d_in, const int* in_sizes, int n_in,
                              void* d_out, int out_size)
{
    const float* atoms = (const float*)d_in[0];
    const int*   conn  = (const int*)d_in[1];
    const int*   batch = (const int*)d_in[2];
    const float* W_exp = (const float*)d_in[3];
    const float* b_exp = (const float*)d_in[4];
    const float* Ws    = (const float*)d_in[5];
    const float* bs    = (const float*)d_in[6];
    float* out = (float*)d_out;

    __half *py, *papk, *pwpk;
    cudaGetSymbolAddress((void**)&py,   g_y);
    cudaGetSymbolAddress((void**)&papk, g_apk);
    cudaGetSymbolAddress((void**)&pwpk, g_wpk);

    k_prep_hist<<<PWB + HB, 256>>>(Ws, conn + EE, batch);
    k_scan<<<SCAN_NB, SCAN_BS>>>();
    k_csr_expand<<<CSRB + EXPB, 256>>>(conn, batch, out, out_size, atoms, W_exp, b_exp);

    int tail = out_size - (DENSE + MASKN);
    if (tail > 0)
        k_zero_tail<<<(tail + 255)/256, 256>>>(out, DENSE + MASKN, tail);

    int aggBlocks = (NN*32 + 255)/256;
    for (int l = 0; l < NLAYERS - 1; l++) {
        k_agg<<<aggBlocks, 256>>>(py);
        k_gemm_mma<false><<<GEMM_NB, 256>>>(papk, pwpk + l*DD*DD, bs + l*DD, py, nullptr, batch);
    }
    k_agg<<<aggBlocks, 256>>>(py);
    k_gemm_mma<true><<<GEMM_NB, 256>>>(papk, pwpk + 4*DD*DD, bs + 4*DD, nullptr, out, batch);
}

// round 17
// speedup vs baseline: 1.0417x; 1.0417x over previous
#include <cuda_runtime.h>
#include <cuda_fp16.h>
#include <cstdint>

#define NN   50000
#define EE   600000
#define FEAT 11
#define DD   128
#define BBATCH 500
#define MAXA 100
#define NLAYERS 5
#define DENSE (BBATCH*MAXA*DD)   /* 6,400,000 */
#define MASKN (BBATCH*MAXA)      /* 50,000 */

#define SCAN_BS   1024
#define SCAN_NB   ((NN + SCAN_BS - 1) / SCAN_BS)   /* 49 */
#define SCAN_FLAG (1 << 30)

#define TILE_M    128
#define GEMM_NB   ((NN + TILE_M - 1) / TILE_M)     /* 391 */
#define NNP       (GEMM_NB * TILE_M)               /* 50048, padded */

// merged-kernel block ranges
#define PWB  ((NLAYERS*DD*DD + 255)/256)           /* 320  prepw blocks  */
#define HB   ((EE + 255)/256)                      /* 2344 hist blocks   */
#define CSRB ((EE + 255)/256)                      /* 2344 csr blocks    */
#define EXPB ((NN + 31)/32)                        /* 1563 expand blocks (4 nodes/warp) */

// -------- scratch (static device globals; zero-initialized, no runtime alloc) --------
// INVARIANT across graph replays: g_deg == 0, g_counts == 0, g_bsum == 0 at entry.
__device__ __half g_y[NN*DD];                  // y = dinv * x, fp16 (12.8 MB)
__device__ __half g_apk[NNP*DD];               // aggregated A, fp16 (pad rows stay 0)
__device__ __half g_wpk[NLAYERS*DD*DD];        // Wt [l][n][k] fp16, fragment-paired word order
__device__ float g_dinv[NN];
__device__ int   g_deg[NN];
__device__ int   g_rowstart[NN+1];
__device__ int   g_cursor[NN];
__device__ int   g_csr_src[EE];
__device__ int   g_counts[BBATCH];
__device__ int   g_ptr[BBATCH];
__device__ int   g_bsum[SCAN_NB];

// ---------------- prep: W transpose + degree/count histogram (merged) ----------------
__global__ void k_prep_hist(const float* __restrict__ Ws,
                            const int* __restrict__ col, const int* __restrict__ batch)
{
    if (blockIdx.x < PWB) {
        int idx = blockIdx.x * 256 + threadIdx.x;
        if (idx >= NLAYERS*DD*DD) return;
        int l = idx >> 14;
        int r = idx & 16383;
        int n = r >> 7;
        int k = r & 127;
        float v = Ws[l*DD*DD + k*DD + n];
        int w = k >> 1;
        int p = ((w >> 3) << 2) | (w & 3);
        int c = (w >> 2) & 1;
        int dst = (l*DD + n) * DD + p*4 + c*2 + (k & 1);
        g_wpk[dst] = __float2half_rn(v);
        return;
    }
    int i = (blockIdx.x - PWB) * 256 + threadIdx.x;
    if (i < EE) atomicAdd(&g_deg[col[i]], 1);
    if (i < NN) atomicAdd(&g_counts[batch[i]], 1);
}

// -------- fused scan: local scan + flagged publish + predecessor poll + apply --------
__global__ __launch_bounds__(SCAN_BS)
void k_scan()
{
    __shared__ int warp_sums[32];
    __shared__ int s_boff;
    int tid  = threadIdx.x;
    int lane = tid & 31;
    int wid  = tid >> 5;
    int i    = blockIdx.x * SCAN_BS + tid;

    int v0 = (i < NN) ? g_deg[i] : 0;
    if (i < NN) {
        g_dinv[i] = rsqrtf((float)v0 + 2.0f);
        g_deg[i]  = 0;                       // restore invariant
    }
    int v  = v0;
    #pragma unroll
    for (int off = 1; off < 32; off <<= 1) {
        int t = __shfl_up_sync(0xffffffffu, v, off);
        if (lane >= off) v += t;
    }
    if (lane == 31) warp_sums[wid] = v;
    __syncthreads();
    if (wid == 0) {
        int s = warp_sums[lane];
        #pragma unroll
        for (int off = 1; off < 32; off <<= 1) {
            int t = __shfl_up_sync(0xffffffffu, s, off);
            if (lane >= off) s += t;
        }
        warp_sums[lane] = s;
    }
    __syncthreads();
    int incl = v + (wid ? warp_sums[wid-1] : 0);

    if (tid == 0) {
        int total = warp_sums[31];
        atomicExch(&g_bsum[blockIdx.x], total | SCAN_FLAG);
    }

    if (wid == 1) {
        int sum = 0;
        for (int p = lane; p < blockIdx.x; p += 32) {
            int bv;
            do { bv = atomicAdd(&g_bsum[p], 0); } while (!(bv & SCAN_FLAG));
            sum += bv & ~SCAN_FLAG;
        }
        #pragma unroll
        for (int off = 16; off > 0; off >>= 1)
            sum += __shfl_down_sync(0xffffffffu, sum, off);
        if (lane == 0) s_boff = sum;
    }
    __syncthreads();
    int boff = s_boff;

    if (i < NN) {
        g_rowstart[i+1] = incl + boff;
        g_cursor[i]     = incl - v0 + boff;
    }

    if (blockIdx.x == 0) {
        if (tid == 0) g_rowstart[0] = 0;
        int c = (tid < BBATCH) ? g_counts[tid] : 0;
        int vv = c;
        #pragma unroll
        for (int off = 1; off < 32; off <<= 1) {
            int t = __shfl_up_sync(0xffffffffu, vv, off);
            if (lane >= off) vv += t;
        }
        __syncthreads();
        if (lane == 31) warp_sums[wid] = vv;
        __syncthreads();
        if (wid == 0) {
            int s = warp_sums[lane];
            #pragma unroll
            for (int off = 1; off < 32; off <<= 1) {
                int t = __shfl_up_sync(0xffffffffu, s, off);
                if (lane >= off) s += t;
            }
            warp_sums[lane] = s;
        }
        __syncthreads();
        int incl2 = vv + (wid ? warp_sums[wid-1] : 0);
        if (tid < BBATCH) {
            g_ptr[tid]    = incl2 - c;
            g_counts[tid] = 0;
        }
    }
}

// ---- merged: csr build + mask write + log-expansion (4 nodes/warp) ----
__global__ __launch_bounds__(256)
void k_csr_expand(const int* __restrict__ conn, const int* __restrict__ batch,
                  float* __restrict__ out, int out_size,
                  const float* __restrict__ atoms,
                  const float* __restrict__ Wexp,
                  const float* __restrict__ bexp)
{
    __shared__ float sW[FEAT*DD];
    __shared__ float sb[DD];

    if (blockIdx.x < CSRB) {
        int e = blockIdx.x * 256 + threadIdx.x;
        if (blockIdx.x == 0 && threadIdx.x < SCAN_NB)
            g_bsum[threadIdx.x] = 0;
        if (e < NN && out_size >= DENSE + MASKN) {
            int b = batch[e];
            out[DENSE + b*MAXA + (e - g_ptr[b])] = 1.0f;
        }
        if (e >= EE) return;
        int r = conn[e];
        int c = conn[EE + e];
        int slot = atomicAdd(&g_cursor[c], 1);
        g_csr_src[slot] = r;
        return;
    }

    int tid = threadIdx.x;
    for (int i = tid; i < FEAT*DD; i += 256) sW[i] = Wexp[i];
    if (tid < DD) sb[tid] = bexp[tid];
    __syncthreads();

    int nb   = blockIdx.x - CSRB;
    int wid  = tid >> 5;
    int lane = tid & 31;
    int d0   = lane * 4;

    #pragma unroll
    for (int it = 0; it < 4; it++) {
        int n = nb * 32 + wid * 4 + it;
        if (n >= NN) break;

        float la = 0.f;
        if (lane < FEAT) la = logf(atoms[n*FEAT + lane] + 1.0f);

        float acc[4];
        #pragma unroll
        for (int q = 0; q < 4; q++) acc[q] = sb[d0 + q];
        #pragma unroll
        for (int f = 0; f < FEAT; f++) {
            float lf = __shfl_sync(0xffffffffu, la, f);
            #pragma unroll
            for (int q = 0; q < 4; q++)
                acc[q] = fmaf(lf, sW[f*DD + d0 + q], acc[q]);
        }
        float di = g_dinv[n];
        __half2 h0 = __floats2half2_rn(acc[0]*di, acc[1]*di);
        __half2 h1 = __floats2half2_rn(acc[2]*di, acc[3]*di);
        uint2 p;
        p.x = *reinterpret_cast<uint32_t*>(&h0);
        p.y = *reinterpret_cast<uint32_t*>(&h1);
        reinterpret_cast<uint2*>(g_y)[n*32 + lane] = p;
    }
}

// ------- aggregation: agg[w] = dinv[w]*(sum_src y[src] + 2*y[w]) -------
// R15 form (per-edge broadcast index LDGs, MLP=8 gathers, fp16 pair pre-add)
// + software-pipelined index prefetch: next batch's 8 indices are loaded while
// the current batch's gathers are in flight. Accumulation order identical to R15.
__global__ void k_agg(const __half* __restrict__ y)
{
    int w = (blockIdx.x * blockDim.x + threadIdx.x) >> 5;
    if (w >= NN) return;
    int lane = threadIdx.x & 31;
    const uint2* yr = reinterpret_cast<const uint2*>(y);

    uint2 sv = yr[w*32 + lane];
    float2 s0 = __half22float2(*reinterpret_cast<__half2*>(&sv.x));
    float2 s1 = __half22float2(*reinterpret_cast<__half2*>(&sv.y));
    float4 acc = make_float4(2.f*s0.x, 2.f*s0.y, 2.f*s1.x, 2.f*s1.y);

    int s = g_rowstart[w];
    int e = g_rowstart[w+1];
    int jend8 = s + ((e - s) & ~7);
    int j = s;

    int nid[8];
    if (j < jend8) {
        #pragma unroll
        for (int q = 0; q < 8; q++) nid[q] = g_csr_src[j + q];
    }
    while (j < jend8) {
        int id[8];
        #pragma unroll
        for (int q = 0; q < 8; q++) id[q] = nid[q];
        j += 8;
        if (j < jend8) {
            #pragma unroll
            for (int q = 0; q < 8; q++) nid[q] = g_csr_src[j + q];
        }
        uint2 u[8];
        #pragma unroll
        for (int q = 0; q < 8; q++) u[q] = yr[id[q]*32 + lane];
        #pragma unroll
        for (int q = 0; q < 4; q++) {
            __half2 px = __hadd2(*reinterpret_cast<__half2*>(&u[2*q].x),
                                 *reinterpret_cast<__half2*>(&u[2*q+1].x));
            __half2 py = __hadd2(*reinterpret_cast<__half2*>(&u[2*q].y),
                                 *reinterpret_cast<__half2*>(&u[2*q+1].y));
            float2 fx = __half22float2(px);
            float2 fy = __half22float2(py);
            acc.x += fx.x; acc.y += fx.y; acc.z += fy.x; acc.w += fy.y;
        }
    }
    for (; j + 2 <= e; j += 2) {
        int   i0 = g_csr_src[j], i1 = g_csr_src[j+1];
        uint2 u0 = yr[i0*32 + lane];
        uint2 u1 = yr[i1*32 + lane];
        __half2 px = __hadd2(*reinterpret_cast<__half2*>(&u0.x),
                             *reinterpret_cast<__half2*>(&u1.x));
        __half2 py = __hadd2(*reinterpret_cast<__half2*>(&u0.y),
                             *reinterpret_cast<__half2*>(&u1.y));
        float2 fx = __half22float2(px);
        float2 fy = __half22float2(py);
        acc.x += fx.x; acc.y += fx.y; acc.z += fy.x; acc.w += fy.y;
    }
    if (j < e) {
        int   src = g_csr_src[j];
        uint2 u   = yr[src*32 + lane];
        float2 a  = __half22float2(*reinterpret_cast<__half2*>(&u.x));
        float2 b  = __half22float2(*reinterpret_cast<__half2*>(&u.y));
        acc.x += a.x; acc.y += a.y; acc.z += b.x; acc.w += b.y;
    }

    float di = g_dinv[w];
    __half2 h0 = __floats2half2_rn(acc.x*di, acc.y*di);
    __half2 h1 = __floats2half2_rn(acc.z*di, acc.w*di);
    uint2 p;
    p.x = *reinterpret_cast<uint32_t*>(&h0);
    p.y = *reinterpret_cast<uint32_t*>(&h1);
    reinterpret_cast<uint2*>(g_apk)[w*32 + lane] = p;
}

// ---------------- fp16 mma.sync GEMM (single term): relu(A W^T + b) ----------------
__device__ __forceinline__ void mma_f16(float* d, const uint32_t* a, const uint32_t* b)
{
    asm volatile(
        "mma.sync.aligned.m16n8k16.row.col.f32.f16.f16.f32 "
        "{%0,%1,%2,%3}, {%4,%5,%6,%7}, {%8,%9}, {%0,%1,%2,%3};"
        : "+f"(d[0]), "+f"(d[1]), "+f"(d[2]), "+f"(d[3])
        : "r"(a[0]), "r"(a[1]), "r"(a[2]), "r"(a[3]), "r"(b[0]), "r"(b[1]));
}

// non-LAST: writes y = dinv*relu(..) as fp16. LAST: scatters fp32 into dense out.
template<bool LAST>
__global__ __launch_bounds__(256)
void k_gemm_mma(const __half* __restrict__ apk,
                const __half* __restrict__ wpk,
                const float* __restrict__ bias,
                __half* __restrict__ yout,
                float* __restrict__ dout,
                const int* __restrict__ batch)
{
    int tid    = threadIdx.x;
    int lane   = tid & 31;
    int wid    = tid >> 5;
    int warp_m = wid & 3;
    int warp_n = wid >> 2;
    int g      = lane >> 2;
    int tq     = lane & 3;

    int rowBase = blockIdx.x * TILE_M + warp_m * 32;
    int colBase = warp_n * 64;

    const uint32_t* AP = reinterpret_cast<const uint32_t*>(apk);
    const uint2*    BP = reinterpret_cast<const uint2*>(wpk);

    const uint32_t* a0 = AP + (rowBase + g     ) * 64;
    const uint32_t* a1 = AP + (rowBase + g +  8) * 64;
    const uint32_t* a2 = AP + (rowBase + g + 16) * 64;
    const uint32_t* a3 = AP + (rowBase + g + 24) * 64;
    const uint2*    bp = BP + (colBase + g) * 32;

    float d[2][8][4];
    #pragma unroll
    for (int mt = 0; mt < 2; mt++)
        #pragma unroll
        for (int nt = 0; nt < 8; nt++)
            #pragma unroll
            for (int q = 0; q < 4; q++) d[mt][nt][q] = 0.0f;

    #pragma unroll 4
    for (int ks = 0; ks < 8; ks++) {
        int o0 = ks*8 + tq;
        int o1 = o0 + 4;

        uint32_t aF[2][4];
        aF[0][0] = a0[o0]; aF[0][1] = a1[o0]; aF[0][2] = a0[o1]; aF[0][3] = a1[o1];
        aF[1][0] = a2[o0]; aF[1][1] = a3[o0]; aF[1][2] = a2[o1]; aF[1][3] = a3[o1];

        uint32_t bF[8][2];
        #pragma unroll
        for (int nt = 0; nt < 8; nt++) {
            uint2 wv = bp[nt*256 + ks*4 + tq];
            bF[nt][0] = wv.x; bF[nt][1] = wv.y;
        }
        #pragma unroll
        for (int mt = 0; mt < 2; mt++)
            #pragma unroll
            for (int nt = 0; nt < 8; nt++)
                mma_f16(d[mt][nt], aF[mt], bF[nt]);
    }

    #pragma unroll
    for (int mt = 0; mt < 2; mt++) {
        int m0 = rowBase + mt*16 + g;
        int m1 = m0 + 8;
        if (LAST) {
            int or0 = 0, or1 = 0;
            if (m0 < NN) { int b = batch[m0]; or0 = b*MAXA + (m0 - g_ptr[b]); }
            if (m1 < NN) { int b = batch[m1]; or1 = b*MAXA + (m1 - g_ptr[b]); }
            #pragma unroll
            for (int nt = 0; nt < 8; nt++) {
                int cn = colBase + nt*8 + tq*2;
                float2 bv = *reinterpret_cast<const float2*>(bias + cn);
                if (m0 < NN) {
                    float2 o;
                    o.x = fmaxf(d[mt][nt][0] + bv.x, 0.f);
                    o.y = fmaxf(d[mt][nt][1] + bv.y, 0.f);
                    *reinterpret_cast<float2*>(dout + or0*DD + cn) = o;
                }
                if (m1 < NN) {
                    float2 o;
                    o.x = fmaxf(d[mt][nt][2] + bv.x, 0.f);
                    o.y = fmaxf(d[mt][nt][3] + bv.y, 0.f);
                    *reinterpret_cast<float2*>(dout + or1*DD + cn) = o;
                }
            }
        } else {
            float di0 = (m0 < NN) ? g_dinv[m0] : 0.f;
            float di1 = (m1 < NN) ? g_dinv[m1] : 0.f;
            #pragma unroll
            for (int nt = 0; nt < 8; nt++) {
                int cn = colBase + nt*8 + tq*2;
                float2 bv = *reinterpret_cast<const float2*>(bias + cn);
                if (m0 < NN) {
                    float ox = fmaxf(d[mt][nt][0] + bv.x, 0.f) * di0;
                    float oy = fmaxf(d[mt][nt][1] + bv.y, 0.f) * di0;
                    *reinterpret_cast<__half2*>(yout + m0*DD + cn) = __floats2half2_rn(ox, oy);
                }
                if (m1 < NN) {
                    float ox = fmaxf(d[mt][nt][2] + bv.x, 0.f) * di1;
                    float oy = fmaxf(d[mt][nt][3] + bv.y, 0.f) * di1;
                    *reinterpret_cast<__half2*>(yout + m1*DD + cn) = __floats2half2_rn(ox, oy);
                }
            }
        }
    }
}

// ---------------- tail zero (only for any region beyond dense+mask) ----------------
__global__ void k_zero_tail(float* __restrict__ out, int start, int n)
{
    int i = blockIdx.x * blockDim.x + threadIdx.x;
    if (i < n) out[start + i] = 0.0f;
}

// ---------------- launch ----------------
extern "C" void kernel_launch(void* const* d_in, const int* in_sizes, int n_in,
                              void* d_out, int out_size)
{
    const float* atoms = (const float*)d_in[0];
    const int*   conn  = (const int*)d_in[1];
    const int*   batch = (const int*)d_in[2];
    const float* W_exp = (const float*)d_in[3];
    const float* b_exp = (const float*)d_in[4];
    const float* Ws    = (const float*)d_in[5];
    const float* bs    = (const float*)d_in[6];
    float* out = (float*)d_out;

    __half *py, *papk, *pwpk;
    cudaGetSymbolAddress((void**)&py,   g_y);
    cudaGetSymbolAddress((void**)&papk, g_apk);
    cudaGetSymbolAddress((void**)&pwpk, g_wpk);

    k_prep_hist<<<PWB + HB, 256>>>(Ws, conn + EE, batch);
    k_scan<<<SCAN_NB, SCAN_BS>>>();
    k_csr_expand<<<CSRB + EXPB, 256>>>(conn, batch, out, out_size, atoms, W_exp, b_exp);

    int tail = out_size - (DENSE + MASKN);
    if (tail > 0)
        k_zero_tail<<<(tail + 255)/256, 256>>>(out, DENSE + MASKN, tail);

    int aggBlocks = (NN*32 + 255)/256;
    for (int l = 0; l < NLAYERS - 1; l++) {
        k_agg<<<aggBlocks, 256>>>(py);
        k_gemm_mma<false><<<GEMM_NB, 256>>>(papk, pwpk + l*DD*DD, bs + l*DD, py, nullptr, batch);
    }
    k_agg<<<aggBlocks, 256>>>(py);
    k_gemm_mma<true><<<GEMM_NB, 256>>>(papk, pwpk + 4*DD*DD, bs + 4*DD, nullptr, out, batch);
}